// round 7
// baseline (speedup 1.0000x reference)
#include <cuda_runtime.h>
#include <cstddef>

#define B_   1024
#define T_   2048
#define CIN  9
#define C1   16
#define C2   32
#define RT   512
#define HID  128
#define OUTF 64

#define DINV2 0.7071067811865475f
#define DINV3 0.5773502691896258f

// ---------------- scratch ----------------
__device__ float g_h1[(size_t)B_ * C1 * 1024];   // conv1 pooled out (tf32-rounded)
__device__ float g_h2[(size_t)B_ * RT * C2];     // conv2 pooled out, node-major
__device__ float g_meanp[(size_t)B_ * 2 * HID];  // per-sample per-t-half partial sums

// ---------------- helpers ----------------
__device__ __forceinline__ unsigned f2tf32(float x) {
    unsigned u; asm("cvt.rna.tf32.f32 %0, %1;" : "=r"(u) : "f"(x)); return u;
}
__device__ __forceinline__ void mma_tf32(float c[4], unsigned a0, unsigned a1,
                                         unsigned a2, unsigned a3,
                                         unsigned b0, unsigned b1) {
    asm volatile("mma.sync.aligned.m16n8k8.row.col.f32.tf32.tf32.f32 "
                 "{%0,%1,%2,%3},{%4,%5,%6,%7},{%8,%9},{%0,%1,%2,%3};"
                 : "+f"(c[0]), "+f"(c[1]), "+f"(c[2]), "+f"(c[3])
                 : "r"(a0), "r"(a1), "r"(a2), "r"(a3), "r"(b0), "r"(b1));
}
// symmetric-normalized 3-pt stencil along t (chain graph + self loop)
__device__ __forceinline__ float stencil_apply(int t, float L, float S, float R) {
    float dt = (t == 0 || t == RT - 1) ? DINV2 : DINV3;
    float cL = (t > 0)      ? dt * ((t - 1 == 0)      ? DINV2 : DINV3) : 0.f;
    float cR = (t < RT - 1) ? dt * ((t + 1 == RT - 1) ? DINV2 : DINV3) : 0.f;
    return fmaf(cL, L, fmaf(dt * dt, S, cR * R));
}

// ================= conv1 (MMA): 9->16 k5 pad2 + relu + maxpool2 =================
#define XS1_STRIDE 524
__global__ void __launch_bounds__(256) conv1_kernel(const float* __restrict__ x,
                                                    const float* __restrict__ w,
                                                    const float* __restrict__ bias) {
    const int b = blockIdx.y, cx = blockIdx.x;
    __shared__ float xs[10 * XS1_STRIDE];
    const int tid = threadIdx.x;

    const float* xb = x + (size_t)b * CIN * T_;
    for (int i = tid; i < 10 * 516; i += 256) {
        int r = i / 516, j = i % 516;
        int tg = cx * 512 + j - 2;
        float v = (r < 9 && (unsigned)tg < T_) ? xb[r * T_ + tg] : 0.f;
        xs[r * XS1_STRIDE + j] = __uint_as_float(f2tf32(v));
    }

    const int lane = tid & 31, warp = tid >> 5;
    const int gq = lane >> 2, tq = lane & 3;

    unsigned aw[6][4];
    int boff0[6], boff1[6];
#pragma unroll
    for (int ks = 0; ks < 6; ks++) {
        int k0 = ks * 8 + tq, k1 = k0 + 4;
        aw[ks][0] = (k0 < 45) ? f2tf32(w[gq * 45 + k0])       : 0u;
        aw[ks][1] = (k0 < 45) ? f2tf32(w[(gq + 8) * 45 + k0]) : 0u;
        aw[ks][2] = (k1 < 45) ? f2tf32(w[gq * 45 + k1])       : 0u;
        aw[ks][3] = (k1 < 45) ? f2tf32(w[(gq + 8) * 45 + k1]) : 0u;
        boff0[ks] = (k0 / 5) * XS1_STRIDE + (k0 % 5);
        boff1[ks] = (k1 / 5) * XS1_STRIDE + (k1 % 5);
    }
    const float bv0 = bias[gq], bv1 = bias[gq + 8];
    __syncthreads();

    float* out0 = g_h1 + ((size_t)b * C1 + gq) * 1024 + cx * 256;
    float* out1 = g_h1 + ((size_t)b * C1 + gq + 8) * 1024 + cx * 256;

#pragma unroll
    for (int j = 0; j < 8; j += 2) {
        const int ntA = warp * 8 + j;
        float accA[4] = {0.f, 0.f, 0.f, 0.f}, accB[4] = {0.f, 0.f, 0.f, 0.f};
#pragma unroll
        for (int ks = 0; ks < 6; ks++) {
            int pA = ntA * 8 + gq;
            unsigned bA0 = __float_as_uint(xs[boff0[ks] + pA]);
            unsigned bA1 = __float_as_uint(xs[boff1[ks] + pA]);
            unsigned bB0 = __float_as_uint(xs[boff0[ks] + pA + 8]);
            unsigned bB1 = __float_as_uint(xs[boff1[ks] + pA + 8]);
            mma_tf32(accA, aw[ks][0], aw[ks][1], aw[ks][2], aw[ks][3], bA0, bA1);
            mma_tf32(accB, aw[ks][0], aw[ks][1], aw[ks][2], aw[ks][3], bB0, bB1);
        }
        int ppA = ntA * 4 + tq, ppB = ppA + 4;
        out0[ppA] = __uint_as_float(f2tf32(fmaxf(fmaxf(accA[0], accA[1]) + bv0, 0.f)));
        out1[ppA] = __uint_as_float(f2tf32(fmaxf(fmaxf(accA[2], accA[3]) + bv1, 0.f)));
        out0[ppB] = __uint_as_float(f2tf32(fmaxf(fmaxf(accB[0], accB[1]) + bv0, 0.f)));
        out1[ppB] = __uint_as_float(f2tf32(fmaxf(fmaxf(accB[2], accB[3]) + bv1, 0.f)));
    }
}

// ================= conv2 (MMA): 16->32 k5 pad2 + relu + maxpool2 =================
#define XS2_STRIDE 524
#define WS2_STRIDE 84
__global__ void __launch_bounds__(256) conv2_kernel(const float* __restrict__ w,
                                                    const float* __restrict__ bias) {
    const int b = blockIdx.y, cx = blockIdx.x;
    __shared__ float xs[16 * XS2_STRIDE];
    __shared__ float Ws[32 * WS2_STRIDE];
    const int tid = threadIdx.x;

    const float* hb = g_h1 + (size_t)b * C1 * 1024;
    for (int i = tid; i < 16 * 516; i += 256) {
        int r = i / 516, j = i % 516;
        int tg = cx * 512 + j - 2;
        xs[r * XS2_STRIDE + j] = ((unsigned)tg < 1024) ? hb[r * 1024 + tg] : 0.f;
    }
    for (int i = tid; i < 32 * 80; i += 256) {
        int co = i / 80, k = i % 80;
        Ws[co * WS2_STRIDE + k] = __uint_as_float(f2tf32(w[i]));
    }

    const int lane = tid & 31, warp = tid >> 5;
    const int gq = lane >> 2, tq = lane & 3;

    int boff0[10], boff1[10];
#pragma unroll
    for (int ks = 0; ks < 10; ks++) {
        int k0 = ks * 8 + tq, k1 = k0 + 4;
        boff0[ks] = (k0 / 5) * XS2_STRIDE + (k0 % 5);
        boff1[ks] = (k1 / 5) * XS2_STRIDE + (k1 % 5);
    }
    const float bvA0 = bias[gq],      bvA1 = bias[gq + 8];
    const float bvB0 = bias[16 + gq], bvB1 = bias[24 + gq];
    __syncthreads();

#pragma unroll
    for (int j = 0; j < 8; j += 2) {
        const int ntA = warp * 8 + j;
        float acc[2][2][4];
#pragma unroll
        for (int m = 0; m < 2; m++)
#pragma unroll
            for (int n = 0; n < 2; n++)
#pragma unroll
                for (int q = 0; q < 4; q++) acc[m][n][q] = 0.f;

#pragma unroll
        for (int ks = 0; ks < 10; ks++) {
            unsigned af[2][4];
#pragma unroll
            for (int m = 0; m < 2; m++) {
                int co0 = m * 16 + gq;
                af[m][0] = __float_as_uint(Ws[co0 * WS2_STRIDE + ks * 8 + tq]);
                af[m][1] = __float_as_uint(Ws[(co0 + 8) * WS2_STRIDE + ks * 8 + tq]);
                af[m][2] = __float_as_uint(Ws[co0 * WS2_STRIDE + ks * 8 + tq + 4]);
                af[m][3] = __float_as_uint(Ws[(co0 + 8) * WS2_STRIDE + ks * 8 + tq + 4]);
            }
            int pA = ntA * 8 + gq;
            unsigned bA0 = __float_as_uint(xs[boff0[ks] + pA]);
            unsigned bA1 = __float_as_uint(xs[boff1[ks] + pA]);
            unsigned bB0 = __float_as_uint(xs[boff0[ks] + pA + 8]);
            unsigned bB1 = __float_as_uint(xs[boff1[ks] + pA + 8]);
            mma_tf32(acc[0][0], af[0][0], af[0][1], af[0][2], af[0][3], bA0, bA1);
            mma_tf32(acc[1][0], af[1][0], af[1][1], af[1][2], af[1][3], bA0, bA1);
            mma_tf32(acc[0][1], af[0][0], af[0][1], af[0][2], af[0][3], bB0, bB1);
            mma_tf32(acc[1][1], af[1][0], af[1][1], af[1][2], af[1][3], bB0, bB1);
        }
        const size_t tb = (size_t)b * RT + cx * 256;
#pragma unroll
        for (int n = 0; n < 2; n++) {
            int t = (int)(ntA + n) * 4 + tq;
            float* g = g_h2 + (tb + t) * C2;
            g[gq]      = fmaxf(fmaxf(acc[0][n][0], acc[0][n][1]) + bvA0, 0.f);
            g[gq + 8]  = fmaxf(fmaxf(acc[0][n][2], acc[0][n][3]) + bvA1, 0.f);
            g[gq + 16] = fmaxf(fmaxf(acc[1][n][0], acc[1][n][1]) + bvB0, 0.f);
            g[gq + 24] = fmaxf(fmaxf(acc[1][n][2], acc[1][n][3]) + bvB1, 0.f);
        }
    }
}

// ======== fused GCN1 + GCN2 + mean: 16 warps = 8 feature-groups x 2 t-halves ========
// Each t-half covers 5 of 9 n-tiles (tile 4 redundant) so stencil neighbors stay
// in-register. Output fragments are [feature][t]; t-stencil via shuffles.
#define SW2   132   // W2s stride (k dim)
#define SG1   72    // g1s stride (t dim)
#define SIN2  36    // in_s stride (c dim)
#define GCN_SMEM_BYTES ((128 * SW2 + 128 * SG1 + 72 * SIN2) * 4)   // 114816

__global__ void __launch_bounds__(512, 2) gcn_fused_kernel(
    const float* __restrict__ W1, const float* __restrict__ b1,
    const float* __restrict__ W2, const float* __restrict__ b2) {
    extern __shared__ float sm[];
    float* W2s  = sm;                        // [128][SW2]  W2^T: W2s[m][k] = W2[k][m]
    float* g1s  = sm + 128 * SW2;            // [128 feats][SG1 t-cols]
    float* in_s = g1s + 128 * SG1;           // [72 t-rows][SIN2]

    const int tid = threadIdx.x;
    const int b = blockIdx.x;
    const int warp = tid >> 5, lane = tid & 31;
    const int gq = lane >> 2, tq = lane & 3;
    const int fgroup = warp >> 1, th = warp & 1;
    const int fbase = fgroup * 16;
    const int ntg0 = th * 4;                 // global n-tile base (tiles ntg0..ntg0+4)
    const int nlo1 = th ? 39 : 1, nhi1 = th ? 66 : 38;   // stencil1 output n-range
    const int nhi2 = th ? 64 : 38;                        // stencil2 (nlo same)
    const unsigned FULL = 0xffffffffu;

    // W2^T into smem (tf32), once per CTA; zero-init g1s (cols 66..71 never written)
    for (int i = tid; i < HID * HID; i += 512) {
        int k = i >> 7, m = i & 127;
        W2s[m * SW2 + k] = __uint_as_float(f2tf32(W2[i]));
    }
    for (int i = tid; i < 128 * SG1; i += 512) g1s[i] = 0.f;
    // W1^T fragments in registers: A(m=feat, k=ci)
    unsigned aw1[4][4];
#pragma unroll
    for (int ks = 0; ks < 4; ks++) {
        int k0 = ks * 8 + tq;
        aw1[ks][0] = f2tf32(W1[k0 * HID + fbase + gq]);
        aw1[ks][1] = f2tf32(W1[k0 * HID + fbase + 8 + gq]);
        aw1[ks][2] = f2tf32(W1[(k0 + 4) * HID + fbase + gq]);
        aw1[ks][3] = f2tf32(W1[(k0 + 4) * HID + fbase + 8 + gq]);
    }
    const float b1v0 = b1[fbase + gq], b1v1 = b1[fbase + 8 + gq];
    const float b2v0 = b2[fbase + gq], b2v1 = b2[fbase + 8 + gq];
    float sum0 = 0.f, sum1 = 0.f;
    __syncthreads();

    for (int chunk = 0; chunk < 8; chunk++) {
        const int t0 = chunk * 64;
        // load in: row r <-> t = t0-2+r, 72 rows x 32 feats
        for (int i = tid; i < 72 * 32; i += 512) {
            int r = i >> 5, c = i & 31;
            int t = t0 - 2 + r;
            float v = ((unsigned)t < RT) ? g_h2[((size_t)b * RT + t) * C2 + c] : 0.f;
            in_s[r * SIN2 + c] = __uint_as_float(f2tf32(v));
        }
        __syncthreads();

        // ---- GEMM1: z1[m=16 feats][cols of tiles ntg0..ntg0+4], col n <-> t = t0-2+n ----
        float acc[5][4];
#pragma unroll
        for (int l = 0; l < 5; l++)
#pragma unroll
            for (int q = 0; q < 4; q++) acc[l][q] = 0.f;
#pragma unroll
        for (int ks = 0; ks < 4; ks++)
#pragma unroll
            for (int l = 0; l < 5; l++) {
                int nb = (ntg0 + l) * 8 + gq;
                unsigned bb0 = __float_as_uint(in_s[nb * SIN2 + ks * 8 + tq]);
                unsigned bb1 = __float_as_uint(in_s[nb * SIN2 + ks * 8 + tq + 4]);
                mma_tf32(acc[l], aw1[ks][0], aw1[ks][1], aw1[ks][2], aw1[ks][3], bb0, bb1);
            }

        // ---- stencil1 (cols) + bias + relu + tf32 -> g1s[feat][n-1] for n in [nlo1,nhi1] ----
#pragma unroll
        for (int h = 0; h < 2; h++) {
            const int rowf = fbase + 8 * h + gq;
            const float bv = h ? b1v1 : b1v0;
#pragma unroll
            for (int l = 0; l < 5; l++) {
                float zE = acc[l][2 * h], zO = acc[l][2 * h + 1];
                float pO = __shfl_up_sync(FULL, zO, 1, 4);
                float nEv = __shfl_down_sync(FULL, zE, 1, 4);
                float pT = (l > 0) ? __shfl_sync(FULL, acc[l - 1][2 * h + 1], 3, 4) : 0.f;
                float nT = (l < 4) ? __shfl_sync(FULL, acc[l + 1][2 * h], 0, 4) : 0.f;
                float Le = (tq == 0) ? pT : pO;
                float Ro = (tq == 3) ? nT : nEv;
                int ne = (ntg0 + l) * 8 + 2 * tq;
                int te = t0 - 2 + ne, to = te + 1;
                if (ne >= nlo1 && ne <= nhi1) {
                    float y = ((unsigned)te < RT)
                        ? fmaxf(stencil_apply(te, Le, zE, zO) + bv, 0.f) : 0.f;
                    g1s[rowf * SG1 + ne - 1] = __uint_as_float(f2tf32(y));
                }
                int no = ne + 1;
                if (no >= nlo1 && no <= nhi1) {
                    float y = ((unsigned)to < RT)
                        ? fmaxf(stencil_apply(to, zE, zO, Ro) + bv, 0.f) : 0.f;
                    g1s[rowf * SG1 + no - 1] = __uint_as_float(f2tf32(y));
                }
            }
        }
        __syncthreads();

        // ---- GEMM2: z2[m][cols of tiles ntg0..ntg0+4], col n <-> t = t0-1+n ----
        float acc2[5][4];
#pragma unroll
        for (int l = 0; l < 5; l++)
#pragma unroll
            for (int q = 0; q < 4; q++) acc2[l][q] = 0.f;
#pragma unroll 4
        for (int ks = 0; ks < 16; ks++) {
            int k0 = ks * 8 + tq;
            unsigned a0 = __float_as_uint(W2s[(fbase + gq) * SW2 + k0]);
            unsigned a1 = __float_as_uint(W2s[(fbase + 8 + gq) * SW2 + k0]);
            unsigned a2 = __float_as_uint(W2s[(fbase + gq) * SW2 + k0 + 4]);
            unsigned a3 = __float_as_uint(W2s[(fbase + 8 + gq) * SW2 + k0 + 4]);
#pragma unroll
            for (int l = 0; l < 5; l++) {
                int nb = (ntg0 + l) * 8 + gq;
                unsigned bb0 = __float_as_uint(g1s[k0 * SG1 + nb]);
                unsigned bb1 = __float_as_uint(g1s[(k0 + 4) * SG1 + nb]);
                mma_tf32(acc2[l], a0, a1, a2, a3, bb0, bb1);
            }
        }

        // ---- stencil2 + bias + relu + accumulate mean (n in [nlo1? no: 1..nhi2], t = t0-1+n) ----
#pragma unroll
        for (int h = 0; h < 2; h++) {
            const float bv = h ? b2v1 : b2v0;
            float lsum = 0.f;
#pragma unroll
            for (int l = 0; l < 5; l++) {
                float zE = acc2[l][2 * h], zO = acc2[l][2 * h + 1];
                float pO = __shfl_up_sync(FULL, zO, 1, 4);
                float nEv = __shfl_down_sync(FULL, zE, 1, 4);
                float pT = (l > 0) ? __shfl_sync(FULL, acc2[l - 1][2 * h + 1], 3, 4) : 0.f;
                float nT = (l < 4) ? __shfl_sync(FULL, acc2[l + 1][2 * h], 0, 4) : 0.f;
                float Le = (tq == 0) ? pT : pO;
                float Ro = (tq == 3) ? nT : nEv;
                int ne = (ntg0 + l) * 8 + 2 * tq;
                int te = t0 - 1 + ne, to = te + 1;
                if (ne >= (th ? 39 : 1) && ne <= nhi2)
                    lsum += fmaxf(stencil_apply(te, Le, zE, zO) + bv, 0.f);
                int no = ne + 1;
                if (no >= (th ? 39 : 1) && no <= nhi2)
                    lsum += fmaxf(stencil_apply(to, zE, zO, Ro) + bv, 0.f);
            }
            if (h) sum1 += lsum; else sum0 += lsum;
        }
    }

    // reduce over tq lanes and write per-t-half partial sums
    sum0 += __shfl_xor_sync(FULL, sum0, 1);
    sum0 += __shfl_xor_sync(FULL, sum0, 2);
    sum1 += __shfl_xor_sync(FULL, sum1, 1);
    sum1 += __shfl_xor_sync(FULL, sum1, 2);
    if (tq == 0) {
        g_meanp[((size_t)b * 2 + th) * HID + fbase + gq]     = sum0;
        g_meanp[((size_t)b * 2 + th) * HID + fbase + 8 + gq] = sum1;
    }
}

// ---------------- FC ----------------
__global__ void __launch_bounds__(128) fc_kernel(const float* __restrict__ fcw,
                                                 const float* __restrict__ fcb,
                                                 float* __restrict__ out) {
    const int b = blockIdx.x, tid = threadIdx.x;
    __shared__ float mean_s[HID];
    float s = g_meanp[((size_t)b * 2 + 0) * HID + tid] +
              g_meanp[((size_t)b * 2 + 1) * HID + tid];
    mean_s[tid] = s * (1.f / (float)RT);
    __syncthreads();
    if (tid < OUTF) {
        float acc = fcb[tid];
#pragma unroll 8
        for (int f = 0; f < HID; f++) acc = fmaf(mean_s[f], fcw[f * OUTF + tid], acc);
        out[(size_t)b * OUTF + tid] = acc;
    }
}

// ---------------- launch ----------------
extern "C" void kernel_launch(void* const* d_in, const int* in_sizes, int n_in,
                              void* d_out, int out_size) {
    const float* x       = (const float*)d_in[0];
    const float* conv1_w = (const float*)d_in[1];
    const float* conv1_b = (const float*)d_in[2];
    const float* conv2_w = (const float*)d_in[3];
    const float* conv2_b = (const float*)d_in[4];
    const float* gcn1_w  = (const float*)d_in[5];
    const float* gcn1_b  = (const float*)d_in[6];
    const float* gcn2_w  = (const float*)d_in[7];
    const float* gcn2_b  = (const float*)d_in[8];
    const float* fc_w    = (const float*)d_in[9];
    const float* fc_b    = (const float*)d_in[10];
    float* out = (float*)d_out;

    static bool attr_set = false;
    if (!attr_set) {
        cudaFuncSetAttribute(gcn_fused_kernel,
                             cudaFuncAttributeMaxDynamicSharedMemorySize, GCN_SMEM_BYTES);
        attr_set = true;
    }

    conv1_kernel<<<dim3(4, B_), 256>>>(x, conv1_w, conv1_b);
    conv2_kernel<<<dim3(2, B_), 256>>>(conv2_w, conv2_b);
    gcn_fused_kernel<<<B_, 512, GCN_SMEM_BYTES>>>(gcn1_w, gcn1_b, gcn2_w, gcn2_b);
    fc_kernel<<<B_, 128>>>(fc_w, fc_b, out);
}

// round 9
// speedup vs baseline: 1.2244x; 1.2244x over previous
#include <cuda_runtime.h>
#include <cstddef>

#define B_   1024
#define T_   2048
#define CIN  9
#define C1   16
#define C2   32
#define RT   512
#define HID  128
#define OUTF 64

#define DINV2 0.7071067811865475f
#define DINV3 0.5773502691896258f

// ---------------- scratch ----------------
__device__ float g_h1[(size_t)B_ * C1 * 1024];   // conv1 pooled out (tf32-rounded)
__device__ float g_h2[(size_t)B_ * RT * C2];     // conv2 pooled out, node-major

// ---------------- helpers ----------------
__device__ __forceinline__ unsigned f2tf32(float x) {
    unsigned u; asm("cvt.rna.tf32.f32 %0, %1;" : "=r"(u) : "f"(x)); return u;
}
__device__ __forceinline__ void mma_tf32(float c[4], unsigned a0, unsigned a1,
                                         unsigned a2, unsigned a3,
                                         unsigned b0, unsigned b1) {
    asm volatile("mma.sync.aligned.m16n8k8.row.col.f32.tf32.tf32.f32 "
                 "{%0,%1,%2,%3},{%4,%5,%6,%7},{%8,%9},{%0,%1,%2,%3};"
                 : "+f"(c[0]), "+f"(c[1]), "+f"(c[2]), "+f"(c[3])
                 : "r"(a0), "r"(a1), "r"(a2), "r"(a3), "r"(b0), "r"(b1));
}
__device__ __forceinline__ void cp_async16(unsigned dst, const void* src, int srcbytes) {
    asm volatile("cp.async.ca.shared.global [%0], [%1], 16, %2;"
                 :: "r"(dst), "l"(src), "r"(srcbytes));
}
// symmetric-normalized 3-pt stencil along t (chain graph + self loop)
__device__ __forceinline__ float stencil_apply(int t, float L, float S, float R) {
    float dt = (t == 0 || t == RT - 1) ? DINV2 : DINV3;
    float cL = (t > 0)      ? dt * ((t - 1 == 0)      ? DINV2 : DINV3) : 0.f;
    float cR = (t < RT - 1) ? dt * ((t + 1 == RT - 1) ? DINV2 : DINV3) : 0.f;
    return fmaf(cL, L, fmaf(dt * dt, S, cR * R));
}

// ================= conv1 (MMA): 9->16 k5 pad2 + relu + maxpool2 =================
#define XS1_STRIDE 524
__global__ void __launch_bounds__(256) conv1_kernel(const float* __restrict__ x,
                                                    const float* __restrict__ w,
                                                    const float* __restrict__ bias) {
    const int b = blockIdx.y, cx = blockIdx.x;
    __shared__ float xs[10 * XS1_STRIDE];
    const int tid = threadIdx.x;

    const float* xb = x + (size_t)b * CIN * T_;
    for (int i = tid; i < 10 * 516; i += 256) {
        int r = i / 516, j = i % 516;
        int tg = cx * 512 + j - 2;
        float v = (r < 9 && (unsigned)tg < T_) ? xb[r * T_ + tg] : 0.f;
        xs[r * XS1_STRIDE + j] = __uint_as_float(f2tf32(v));
    }

    const int lane = tid & 31, warp = tid >> 5;
    const int gq = lane >> 2, tq = lane & 3;

    unsigned aw[6][4];
    int boff0[6], boff1[6];
#pragma unroll
    for (int ks = 0; ks < 6; ks++) {
        int k0 = ks * 8 + tq, k1 = k0 + 4;
        aw[ks][0] = (k0 < 45) ? f2tf32(w[gq * 45 + k0])       : 0u;
        aw[ks][1] = (k0 < 45) ? f2tf32(w[(gq + 8) * 45 + k0]) : 0u;
        aw[ks][2] = (k1 < 45) ? f2tf32(w[gq * 45 + k1])       : 0u;
        aw[ks][3] = (k1 < 45) ? f2tf32(w[(gq + 8) * 45 + k1]) : 0u;
        boff0[ks] = (k0 / 5) * XS1_STRIDE + (k0 % 5);
        boff1[ks] = (k1 / 5) * XS1_STRIDE + (k1 % 5);
    }
    const float bv0 = bias[gq], bv1 = bias[gq + 8];
    __syncthreads();

    float* out0 = g_h1 + ((size_t)b * C1 + gq) * 1024 + cx * 256;
    float* out1 = g_h1 + ((size_t)b * C1 + gq + 8) * 1024 + cx * 256;

#pragma unroll
    for (int j = 0; j < 8; j += 2) {
        const int ntA = warp * 8 + j;
        float accA[4] = {0.f, 0.f, 0.f, 0.f}, accB[4] = {0.f, 0.f, 0.f, 0.f};
#pragma unroll
        for (int ks = 0; ks < 6; ks++) {
            int pA = ntA * 8 + gq;
            unsigned bA0 = __float_as_uint(xs[boff0[ks] + pA]);
            unsigned bA1 = __float_as_uint(xs[boff1[ks] + pA]);
            unsigned bB0 = __float_as_uint(xs[boff0[ks] + pA + 8]);
            unsigned bB1 = __float_as_uint(xs[boff1[ks] + pA + 8]);
            mma_tf32(accA, aw[ks][0], aw[ks][1], aw[ks][2], aw[ks][3], bA0, bA1);
            mma_tf32(accB, aw[ks][0], aw[ks][1], aw[ks][2], aw[ks][3], bB0, bB1);
        }
        int ppA = ntA * 4 + tq, ppB = ppA + 4;
        out0[ppA] = __uint_as_float(f2tf32(fmaxf(fmaxf(accA[0], accA[1]) + bv0, 0.f)));
        out1[ppA] = __uint_as_float(f2tf32(fmaxf(fmaxf(accA[2], accA[3]) + bv1, 0.f)));
        out0[ppB] = __uint_as_float(f2tf32(fmaxf(fmaxf(accB[0], accB[1]) + bv0, 0.f)));
        out1[ppB] = __uint_as_float(f2tf32(fmaxf(fmaxf(accB[2], accB[3]) + bv1, 0.f)));
    }
}

// ================= conv2 (MMA): 16->32 k5 pad2 + relu + maxpool2 =================
#define XS2_STRIDE 524
#define WS2_STRIDE 84
__global__ void __launch_bounds__(256) conv2_kernel(const float* __restrict__ w,
                                                    const float* __restrict__ bias) {
    const int b = blockIdx.y, cx = blockIdx.x;
    __shared__ float xs[16 * XS2_STRIDE];
    __shared__ float Ws[32 * WS2_STRIDE];
    const int tid = threadIdx.x;

    const float* hb = g_h1 + (size_t)b * C1 * 1024;
    for (int i = tid; i < 16 * 516; i += 256) {
        int r = i / 516, j = i % 516;
        int tg = cx * 512 + j - 2;
        xs[r * XS2_STRIDE + j] = ((unsigned)tg < 1024) ? hb[r * 1024 + tg] : 0.f;
    }
    for (int i = tid; i < 32 * 80; i += 256) {
        int co = i / 80, k = i % 80;
        Ws[co * WS2_STRIDE + k] = __uint_as_float(f2tf32(w[i]));
    }

    const int lane = tid & 31, warp = tid >> 5;
    const int gq = lane >> 2, tq = lane & 3;

    int boff0[10], boff1[10];
#pragma unroll
    for (int ks = 0; ks < 10; ks++) {
        int k0 = ks * 8 + tq, k1 = k0 + 4;
        boff0[ks] = (k0 / 5) * XS2_STRIDE + (k0 % 5);
        boff1[ks] = (k1 / 5) * XS2_STRIDE + (k1 % 5);
    }
    const float bvA0 = bias[gq],      bvA1 = bias[gq + 8];
    const float bvB0 = bias[16 + gq], bvB1 = bias[24 + gq];
    __syncthreads();

#pragma unroll
    for (int j = 0; j < 8; j += 2) {
        const int ntA = warp * 8 + j;
        float acc[2][2][4];
#pragma unroll
        for (int m = 0; m < 2; m++)
#pragma unroll
            for (int n = 0; n < 2; n++)
#pragma unroll
                for (int q = 0; q < 4; q++) acc[m][n][q] = 0.f;

#pragma unroll
        for (int ks = 0; ks < 10; ks++) {
            unsigned af[2][4];
#pragma unroll
            for (int m = 0; m < 2; m++) {
                int co0 = m * 16 + gq;
                af[m][0] = __float_as_uint(Ws[co0 * WS2_STRIDE + ks * 8 + tq]);
                af[m][1] = __float_as_uint(Ws[(co0 + 8) * WS2_STRIDE + ks * 8 + tq]);
                af[m][2] = __float_as_uint(Ws[co0 * WS2_STRIDE + ks * 8 + tq + 4]);
                af[m][3] = __float_as_uint(Ws[(co0 + 8) * WS2_STRIDE + ks * 8 + tq + 4]);
            }
            int pA = ntA * 8 + gq;
            unsigned bA0 = __float_as_uint(xs[boff0[ks] + pA]);
            unsigned bA1 = __float_as_uint(xs[boff1[ks] + pA]);
            unsigned bB0 = __float_as_uint(xs[boff0[ks] + pA + 8]);
            unsigned bB1 = __float_as_uint(xs[boff1[ks] + pA + 8]);
            mma_tf32(acc[0][0], af[0][0], af[0][1], af[0][2], af[0][3], bA0, bA1);
            mma_tf32(acc[1][0], af[1][0], af[1][1], af[1][2], af[1][3], bA0, bA1);
            mma_tf32(acc[0][1], af[0][0], af[0][1], af[0][2], af[0][3], bB0, bB1);
            mma_tf32(acc[1][1], af[1][0], af[1][1], af[1][2], af[1][3], bB0, bB1);
        }
        const size_t tb = (size_t)b * RT + cx * 256;
#pragma unroll
        for (int n = 0; n < 2; n++) {
            int t = (int)(ntA + n) * 4 + tq;
            float* g = g_h2 + (tb + t) * C2;
            g[gq]      = fmaxf(fmaxf(acc[0][n][0], acc[0][n][1]) + bvA0, 0.f);
            g[gq + 8]  = fmaxf(fmaxf(acc[0][n][2], acc[0][n][3]) + bvA1, 0.f);
            g[gq + 16] = fmaxf(fmaxf(acc[1][n][0], acc[1][n][1]) + bvB0, 0.f);
            g[gq + 24] = fmaxf(fmaxf(acc[1][n][2], acc[1][n][3]) + bvB1, 0.f);
        }
    }
}

// ======== fused GCN1 + GCN2 + mean + FC: feature-major MMA, stencils via shuffles ========
// R5 structure (256 thr, occ 2) + cp.async in_s pipeline + fc folded into epilogue.
#define SW2   132   // W2s stride (k dim)
#define SG1   72    // g1s stride (t dim)
#define SIN2  36    // in_s stride (c dim)
#define GCN_SMEM_BYTES ((128 * SW2 + 128 * SG1 + 72 * SIN2) * 4)   // 114816

__global__ void __launch_bounds__(256, 2) gcn_fused_kernel(
    const float* __restrict__ W1, const float* __restrict__ b1,
    const float* __restrict__ W2, const float* __restrict__ b2,
    const float* __restrict__ fcw, const float* __restrict__ fcb,
    float* __restrict__ out) {
    extern __shared__ float sm[];
    float* W2s  = sm;                        // [128][SW2]  W2^T: W2s[m][k] = W2[k][m]
    float* g1s  = sm + 128 * SW2;            // [128 feats][SG1 t-cols]; fcw staging at end
    float* in_s = g1s + 128 * SG1;           // [72 t-rows][SIN2], raw fp32 via cp.async

    const int tid = threadIdx.x;
    const int b = blockIdx.x;
    const int warp = tid >> 5, lane = tid & 31;
    const int gq = lane >> 2, tq = lane & 3;
    const int fbase = warp * 16;
    const unsigned FULL = 0xffffffffu;
    const unsigned in_sa = (unsigned)__cvta_generic_to_shared(in_s);

    // ---- prefetch chunk 0 (raw fp32; tf32 cvt at consumption) ----
    {
        const int t0 = 0;
#pragma unroll
        for (int it = 0; it < 3; it++) {
            int v = tid + it * 256;
            if (v < 576) {
                int r = v >> 3, c4 = v & 7;
                int t = t0 - 2 + r;
                bool valid = (unsigned)t < RT;
                int tc = valid ? t : 0;
                const float* src = g_h2 + ((size_t)b * RT + tc) * C2 + c4 * 4;
                cp_async16(in_sa + (unsigned)(r * SIN2 + c4 * 4) * 4, src, valid ? 16 : 0);
            }
        }
        asm volatile("cp.async.commit_group;");
    }

    // W2^T into smem (tf32), once per CTA; zero g1s pad cols (66..71 never written)
    for (int i = tid; i < HID * HID; i += 256) {
        int k = i >> 7, m = i & 127;
        W2s[m * SW2 + k] = __uint_as_float(f2tf32(W2[i]));
    }
    for (int i = tid; i < 128 * SG1; i += 256) g1s[i] = 0.f;
    // W1^T fragments in registers: A(m=feat, k=ci)
    unsigned aw1[4][4];
#pragma unroll
    for (int ks = 0; ks < 4; ks++) {
        int k0 = ks * 8 + tq;
        aw1[ks][0] = f2tf32(W1[k0 * HID + fbase + gq]);
        aw1[ks][1] = f2tf32(W1[k0 * HID + fbase + 8 + gq]);
        aw1[ks][2] = f2tf32(W1[(k0 + 4) * HID + fbase + gq]);
        aw1[ks][3] = f2tf32(W1[(k0 + 4) * HID + fbase + 8 + gq]);
    }
    const float b1v0 = b1[fbase + gq], b1v1 = b1[fbase + 8 + gq];
    const float b2v0 = b2[fbase + gq], b2v1 = b2[fbase + 8 + gq];
    float sum0 = 0.f, sum1 = 0.f;

    for (int chunk = 0; chunk < 8; chunk++) {
        const int t0 = chunk * 64;
        asm volatile("cp.async.wait_group 0;");
        __syncthreads();                       // in_s ready; g1s reads of prev chunk done

        // ---- GEMM1: z1[m=16 feats/warp][n=72 t-cols], col n <-> t = t0-2+n ----
        float acc[9][4];
#pragma unroll
        for (int nt = 0; nt < 9; nt++)
#pragma unroll
            for (int q = 0; q < 4; q++) acc[nt][q] = 0.f;
#pragma unroll
        for (int ks = 0; ks < 4; ks++)
#pragma unroll
            for (int nt = 0; nt < 9; nt++) {
                unsigned bb0 = f2tf32(in_s[(nt * 8 + gq) * SIN2 + ks * 8 + tq]);
                unsigned bb1 = f2tf32(in_s[(nt * 8 + gq) * SIN2 + ks * 8 + tq + 4]);
                mma_tf32(acc[nt], aw1[ks][0], aw1[ks][1], aw1[ks][2], aw1[ks][3], bb0, bb1);
            }

        // ---- stencil1 (cols) + bias + relu + tf32 -> g1s[feat][n-1], n in 1..66 ----
#pragma unroll
        for (int h = 0; h < 2; h++) {
            const int rowf = fbase + 8 * h + gq;
            const float bv = h ? b1v1 : b1v0;
#pragma unroll
            for (int nt = 0; nt < 9; nt++) {
                float zE = acc[nt][2 * h], zO = acc[nt][2 * h + 1];
                float pO = __shfl_up_sync(FULL, zO, 1, 4);
                float nEv = __shfl_down_sync(FULL, zE, 1, 4);
                float pT = (nt > 0) ? __shfl_sync(FULL, acc[nt - 1][2 * h + 1], 3, 4) : 0.f;
                float nT = (nt < 8) ? __shfl_sync(FULL, acc[nt + 1][2 * h], 0, 4) : 0.f;
                float Le = (tq == 0) ? pT : pO;
                float Ro = (tq == 3) ? nT : nEv;
                int ne = nt * 8 + 2 * tq;
                int te = t0 - 2 + ne, to = te + 1;
                if (ne >= 2 && ne <= 66) {
                    float y = ((unsigned)te < RT)
                        ? fmaxf(stencil_apply(te, Le, zE, zO) + bv, 0.f) : 0.f;
                    g1s[rowf * SG1 + ne - 1] = __uint_as_float(f2tf32(y));
                }
                int no = ne + 1;
                if (no <= 66) {
                    float y = ((unsigned)to < RT)
                        ? fmaxf(stencil_apply(to, zE, zO, Ro) + bv, 0.f) : 0.f;
                    g1s[rowf * SG1 + no - 1] = __uint_as_float(f2tf32(y));
                }
            }
        }
        __syncthreads();                       // g1s ready; in_s readers done

        // ---- prefetch chunk+1 into in_s (overlaps GEMM2) ----
        if (chunk < 7) {
            const int t0n = (chunk + 1) * 64;
#pragma unroll
            for (int it = 0; it < 3; it++) {
                int v = tid + it * 256;
                if (v < 576) {
                    int r = v >> 3, c4 = v & 7;
                    int t = t0n - 2 + r;
                    bool valid = (unsigned)t < RT;
                    int tc = valid ? t : 0;
                    const float* src = g_h2 + ((size_t)b * RT + tc) * C2 + c4 * 4;
                    cp_async16(in_sa + (unsigned)(r * SIN2 + c4 * 4) * 4, src, valid ? 16 : 0);
                }
            }
            asm volatile("cp.async.commit_group;");
        }

        // ---- GEMM2: z2[m][n=72 t-cols], col n <-> t = t0-1+n; B = g1s, A = W2s ----
        float acc2[9][4];
#pragma unroll
        for (int nt = 0; nt < 9; nt++)
#pragma unroll
            for (int q = 0; q < 4; q++) acc2[nt][q] = 0.f;
#pragma unroll 8
        for (int ks = 0; ks < 16; ks++) {
            int k0 = ks * 8 + tq;
            unsigned a0 = __float_as_uint(W2s[(fbase + gq) * SW2 + k0]);
            unsigned a1 = __float_as_uint(W2s[(fbase + 8 + gq) * SW2 + k0]);
            unsigned a2 = __float_as_uint(W2s[(fbase + gq) * SW2 + k0 + 4]);
            unsigned a3 = __float_as_uint(W2s[(fbase + 8 + gq) * SW2 + k0 + 4]);
#pragma unroll
            for (int nt = 0; nt < 9; nt++) {
                unsigned bb0 = __float_as_uint(g1s[k0 * SG1 + nt * 8 + gq]);
                unsigned bb1 = __float_as_uint(g1s[(k0 + 4) * SG1 + nt * 8 + gq]);
                mma_tf32(acc2[nt], a0, a1, a2, a3, bb0, bb1);
            }
        }

        // ---- stencil2 + bias + relu + accumulate mean (valid n in 1..64, t = t0-1+n) ----
#pragma unroll
        for (int h = 0; h < 2; h++) {
            const float bv = h ? b2v1 : b2v0;
            float lsum = 0.f;
#pragma unroll
            for (int nt = 0; nt < 9; nt++) {
                float zE = acc2[nt][2 * h], zO = acc2[nt][2 * h + 1];
                float pO = __shfl_up_sync(FULL, zO, 1, 4);
                float nEv = __shfl_down_sync(FULL, zE, 1, 4);
                float pT = (nt > 0) ? __shfl_sync(FULL, acc2[nt - 1][2 * h + 1], 3, 4) : 0.f;
                float nT = (nt < 8) ? __shfl_sync(FULL, acc2[nt + 1][2 * h], 0, 4) : 0.f;
                float Le = (tq == 0) ? pT : pO;
                float Ro = (tq == 3) ? nT : nEv;
                int ne = nt * 8 + 2 * tq;
                int te = t0 - 1 + ne, to = te + 1;
                if (ne >= 2 && ne <= 64)
                    lsum += fmaxf(stencil_apply(te, Le, zE, zO) + bv, 0.f);
                int no = ne + 1;
                if (no <= 64)
                    lsum += fmaxf(stencil_apply(to, zE, zO, Ro) + bv, 0.f);
            }
            if (h) sum1 += lsum; else sum0 += lsum;
        }
    }

    // ---- epilogue: mean (in_s reused) + FC (fcw staged in g1s) ----
    sum0 += __shfl_xor_sync(FULL, sum0, 1);
    sum0 += __shfl_xor_sync(FULL, sum0, 2);
    sum1 += __shfl_xor_sync(FULL, sum1, 1);
    sum1 += __shfl_xor_sync(FULL, sum1, 2);
    if (tq == 0) {
        in_s[fbase + gq]     = sum0 * (1.f / (float)RT);
        in_s[fbase + 8 + gq] = sum1 * (1.f / (float)RT);
    }
    __syncthreads();                           // all GEMM2 g1s reads done; means visible
    for (int i = tid; i < HID * OUTF; i += 256) g1s[i] = fcw[i];
    __syncthreads();
    if (tid < OUTF) {
        float acc = fcb[tid];
#pragma unroll 8
        for (int f = 0; f < HID; f++) acc = fmaf(in_s[f], g1s[f * OUTF + tid], acc);
        out[(size_t)b * OUTF + tid] = acc;
    }
}

// ---------------- launch ----------------
extern "C" void kernel_launch(void* const* d_in, const int* in_sizes, int n_in,
                              void* d_out, int out_size) {
    const float* x       = (const float*)d_in[0];
    const float* conv1_w = (const float*)d_in[1];
    const float* conv1_b = (const float*)d_in[2];
    const float* conv2_w = (const float*)d_in[3];
    const float* conv2_b = (const float*)d_in[4];
    const float* gcn1_w  = (const float*)d_in[5];
    const float* gcn1_b  = (const float*)d_in[6];
    const float* gcn2_w  = (const float*)d_in[7];
    const float* gcn2_b  = (const float*)d_in[8];
    const float* fc_w    = (const float*)d_in[9];
    const float* fc_b    = (const float*)d_in[10];
    float* out = (float*)d_out;

    static bool attr_set = false;
    if (!attr_set) {
        cudaFuncSetAttribute(gcn_fused_kernel,
                             cudaFuncAttributeMaxDynamicSharedMemorySize, GCN_SMEM_BYTES);
        attr_set = true;
    }

    conv1_kernel<<<dim3(4, B_), 256>>>(x, conv1_w, conv1_b);
    conv2_kernel<<<dim3(2, B_), 256>>>(conv2_w, conv2_b);
    gcn_fused_kernel<<<B_, 256, GCN_SMEM_BYTES>>>(gcn1_w, gcn1_b, gcn2_w, gcn2_b,
                                                  fc_w, fc_b, out);
}

// round 12
// speedup vs baseline: 1.4615x; 1.1936x over previous
#include <cuda_runtime.h>
#include <cstddef>

#define B_   1024
#define T_   2048
#define CIN  9
#define C1   16
#define C2   32
#define RT   512
#define HID  128
#define OUTF 64

#define DINV2 0.7071067811865475f
#define DINV3 0.5773502691896258f

// ---------------- scratch ----------------
__device__ float g_h2[(size_t)B_ * RT * C2];     // conv2 pooled out, node-major

// ---------------- helpers ----------------
__device__ __forceinline__ unsigned f2tf32(float x) {
    unsigned u; asm("cvt.rna.tf32.f32 %0, %1;" : "=r"(u) : "f"(x)); return u;
}
__device__ __forceinline__ void mma_tf32(float c[4], unsigned a0, unsigned a1,
                                         unsigned a2, unsigned a3,
                                         unsigned b0, unsigned b1) {
    asm volatile("mma.sync.aligned.m16n8k8.row.col.f32.tf32.tf32.f32 "
                 "{%0,%1,%2,%3},{%4,%5,%6,%7},{%8,%9},{%0,%1,%2,%3};"
                 : "+f"(c[0]), "+f"(c[1]), "+f"(c[2]), "+f"(c[3])
                 : "r"(a0), "r"(a1), "r"(a2), "r"(a3), "r"(b0), "r"(b1));
}
__device__ __forceinline__ void cp_async16(unsigned dst, const void* src, int srcbytes) {
    asm volatile("cp.async.ca.shared.global [%0], [%1], 16, %2;"
                 :: "r"(dst), "l"(src), "r"(srcbytes));
}
// symmetric-normalized 3-pt stencil along t (chain graph + self loop), full path
__device__ __forceinline__ float stencil_apply(int t, float L, float S, float R) {
    float dt = (t == 0 || t == RT - 1) ? DINV2 : DINV3;
    float cL = (t > 0)      ? dt * ((t - 1 == 0)      ? DINV2 : DINV3) : 0.f;
    float cR = (t < RT - 1) ? dt * ((t + 1 == RT - 1) ? DINV2 : DINV3) : 0.f;
    return fmaf(cL, L, fmaf(dt * dt, S, cR * R));
}

// ============ fused conv1+conv2 (MMA): x -> h1 (smem) -> g_h2 ============
// Per CTA: one sample b, one half cx of the time axis.
// Stage 1: conv1 9->16 k5 pad2 + relu + maxpool2 over 1032 conv positions -> h1s[16][516]
// Stage 2: conv2 16->32 k5 pad2 + relu + maxpool2 -> g_h2 256 RT positions.
#define XSF_STRIDE 1044      // raw x row stride (needs 1036), mod 32 = 20
#define H1_STRIDE  524       // h1s row stride (needs 516),  mod 32 = 12
#define WS2_STRIDE 84
#define CONV_SMEM_BYTES ((10 * XSF_STRIDE + 16 * H1_STRIDE + 32 * WS2_STRIDE) * 4)

__global__ void __launch_bounds__(256) conv12_kernel(const float* __restrict__ x,
                                                     const float* __restrict__ w1,
                                                     const float* __restrict__ b1c,
                                                     const float* __restrict__ w2,
                                                     const float* __restrict__ b2c) {
    extern __shared__ float smc[];
    float* xs  = smc;                                   // [10][XSF_STRIDE]
    float* h1s = smc + 10 * XSF_STRIDE;                 // [16][H1_STRIDE]
    float* Ws  = h1s + 16 * H1_STRIDE;                  // [32][WS2_STRIDE]

    const int b = blockIdx.y, cx = blockIdx.x;          // cx in {0,1}
    const int tid = threadIdx.x;
    const int lane = tid & 31, warp = tid >> 5;
    const int gq = lane >> 2, tq = lane & 3;
    const int P0 = cx * 512;                            // h1 base position

    // ---- fill raw x (halo 6/..), zero pad; tf32-rounded ----
    const float* xb = x + (size_t)b * CIN * T_;
    for (int i = tid; i < 10 * XSF_STRIDE; i += 256) {
        int r = i / XSF_STRIDE, j = i % XSF_STRIDE;
        int tg = cx * 1024 + j - 6;
        float v = (r < 9 && j < 1036 && (unsigned)tg < T_) ? xb[r * T_ + tg] : 0.f;
        xs[i] = __uint_as_float(f2tf32(v));
    }
    // conv2 weights into smem
    for (int i = tid; i < 32 * 80; i += 256) {
        int co = i / 80, k = i % 80;
        Ws[co * WS2_STRIDE + k] = __uint_as_float(f2tf32(w2[i]));
    }

    // conv1 weight fragments in regs: A = W1[16 co][K=48 (ci,tap) padded]
    unsigned aw[6][4];
    int xoff0[6], xoff1[6];
#pragma unroll
    for (int ks = 0; ks < 6; ks++) {
        int k0 = ks * 8 + tq, k1 = k0 + 4;
        aw[ks][0] = (k0 < 45) ? f2tf32(w1[gq * 45 + k0])       : 0u;
        aw[ks][1] = (k0 < 45) ? f2tf32(w1[(gq + 8) * 45 + k0]) : 0u;
        aw[ks][2] = (k1 < 45) ? f2tf32(w1[gq * 45 + k1])       : 0u;
        aw[ks][3] = (k1 < 45) ? f2tf32(w1[(gq + 8) * 45 + k1]) : 0u;
        xoff0[ks] = (k0 / 5) * XSF_STRIDE + (k0 % 5);
        xoff1[ks] = (k1 / 5) * XSF_STRIDE + (k1 % 5);
    }
    const float c1b0 = b1c[gq], c1b1 = b1c[gq + 8];
    __syncthreads();

    // ---- stage 1: 65 tile-pairs (130 n-tiles of 8 taus); pooled outputs m=pi*8..+7 ----
    for (int pi = warp; pi < 65; pi += 8) {
        const int ntA = pi * 2;
        float accA[4] = {0.f, 0.f, 0.f, 0.f}, accB[4] = {0.f, 0.f, 0.f, 0.f};
#pragma unroll
        for (int ks = 0; ks < 6; ks++) {
            int pA = ntA * 8 + gq;
            unsigned bA0 = __float_as_uint(xs[xoff0[ks] + pA]);
            unsigned bA1 = __float_as_uint(xs[xoff1[ks] + pA]);
            unsigned bB0 = __float_as_uint(xs[xoff0[ks] + pA + 8]);
            unsigned bB1 = __float_as_uint(xs[xoff1[ks] + pA + 8]);
            mma_tf32(accA, aw[ks][0], aw[ks][1], aw[ks][2], aw[ks][3], bA0, bA1);
            mma_tf32(accB, aw[ks][0], aw[ks][1], aw[ks][2], aw[ks][3], bB0, bB1);
        }
        // pooled index m -> h1 position p = P0 - 2 + m; zero outside [0,1024)
        int mA = ntA * 4 + tq, mB = mA + 4;
        if (mA < 516) {
            bool pv = (unsigned)(P0 - 2 + mA) < 1024;
            float v0 = pv ? fmaxf(fmaxf(accA[0], accA[1]) + c1b0, 0.f) : 0.f;
            float v1 = pv ? fmaxf(fmaxf(accA[2], accA[3]) + c1b1, 0.f) : 0.f;
            h1s[gq * H1_STRIDE + mA]       = __uint_as_float(f2tf32(v0));
            h1s[(gq + 8) * H1_STRIDE + mA] = __uint_as_float(f2tf32(v1));
        }
        if (mB < 516) {
            bool pv = (unsigned)(P0 - 2 + mB) < 1024;
            float v0 = pv ? fmaxf(fmaxf(accB[0], accB[1]) + c1b0, 0.f) : 0.f;
            float v1 = pv ? fmaxf(fmaxf(accB[2], accB[3]) + c1b1, 0.f) : 0.f;
            h1s[gq * H1_STRIDE + mB]       = __uint_as_float(f2tf32(v0));
            h1s[(gq + 8) * H1_STRIDE + mB] = __uint_as_float(f2tf32(v1));
        }
    }
    __syncthreads();

    // ---- stage 2: conv2 on h1s ----
    int hoff0[10], hoff1[10];
#pragma unroll
    for (int ks = 0; ks < 10; ks++) {
        int k0 = ks * 8 + tq, k1 = k0 + 4;
        hoff0[ks] = (k0 / 5) * H1_STRIDE + (k0 % 5);
        hoff1[ks] = (k1 / 5) * H1_STRIDE + (k1 % 5);
    }
    const float bvA0 = b2c[gq],      bvA1 = b2c[gq + 8];
    const float bvB0 = b2c[16 + gq], bvB1 = b2c[24 + gq];

#pragma unroll
    for (int j = 0; j < 8; j += 2) {
        const int ntA = warp * 8 + j;
        float acc[2][2][4];
#pragma unroll
        for (int m = 0; m < 2; m++)
#pragma unroll
            for (int n = 0; n < 2; n++)
#pragma unroll
                for (int q = 0; q < 4; q++) acc[m][n][q] = 0.f;

#pragma unroll
        for (int ks = 0; ks < 10; ks++) {
            unsigned af[2][4];
#pragma unroll
            for (int m = 0; m < 2; m++) {
                int co0 = m * 16 + gq;
                af[m][0] = __float_as_uint(Ws[co0 * WS2_STRIDE + ks * 8 + tq]);
                af[m][1] = __float_as_uint(Ws[(co0 + 8) * WS2_STRIDE + ks * 8 + tq]);
                af[m][2] = __float_as_uint(Ws[co0 * WS2_STRIDE + ks * 8 + tq + 4]);
                af[m][3] = __float_as_uint(Ws[(co0 + 8) * WS2_STRIDE + ks * 8 + tq + 4]);
            }
            int pA = ntA * 8 + gq;
            unsigned bA0 = __float_as_uint(h1s[hoff0[ks] + pA]);
            unsigned bA1 = __float_as_uint(h1s[hoff1[ks] + pA]);
            unsigned bB0 = __float_as_uint(h1s[hoff0[ks] + pA + 8]);
            unsigned bB1 = __float_as_uint(h1s[hoff1[ks] + pA + 8]);
            mma_tf32(acc[0][0], af[0][0], af[0][1], af[0][2], af[0][3], bA0, bA1);
            mma_tf32(acc[1][0], af[1][0], af[1][1], af[1][2], af[1][3], bA0, bA1);
            mma_tf32(acc[0][1], af[0][0], af[0][1], af[0][2], af[0][3], bB0, bB1);
            mma_tf32(acc[1][1], af[1][0], af[1][1], af[1][2], af[1][3], bB0, bB1);
        }
        const size_t tb = (size_t)b * RT + cx * 256;
#pragma unroll
        for (int n = 0; n < 2; n++) {
            int t = (int)(ntA + n) * 4 + tq;
            float* g = g_h2 + (tb + t) * C2;
            g[gq]      = fmaxf(fmaxf(acc[0][n][0], acc[0][n][1]) + bvA0, 0.f);
            g[gq + 8]  = fmaxf(fmaxf(acc[0][n][2], acc[0][n][3]) + bvA1, 0.f);
            g[gq + 16] = fmaxf(fmaxf(acc[1][n][0], acc[1][n][1]) + bvB0, 0.f);
            g[gq + 24] = fmaxf(fmaxf(acc[1][n][2], acc[1][n][3]) + bvB1, 0.f);
        }
    }
}

// ======== fused GCN1 + GCN2 + mean + FC: feature-major MMA, stencils via shuffles ========
#define SW2   132   // W2s stride (k dim)
#define SG1   72    // g1s stride (t dim)
#define SIN2  36    // in_s stride (c dim)
#define GCN_SMEM_BYTES ((128 * SW2 + 128 * SG1 + 72 * SIN2) * 4)   // 114816

__global__ void __launch_bounds__(256, 2) gcn_fused_kernel(
    const float* __restrict__ W1, const float* __restrict__ b1,
    const float* __restrict__ W2, const float* __restrict__ b2,
    const float* __restrict__ fcw, const float* __restrict__ fcb,
    float* __restrict__ out) {
    extern __shared__ float sm[];
    float* W2s  = sm;                        // [128][SW2]  W2^T
    float* g1s  = sm + 128 * SW2;            // [128 feats][SG1 t-cols]; fcw staging at end
    float* in_s = g1s + 128 * SG1;           // [72 t-rows][SIN2], raw fp32 via cp.async

    const int tid = threadIdx.x;
    const int b = blockIdx.x;
    const int warp = tid >> 5, lane = tid & 31;
    const int gq = lane >> 2, tq = lane & 3;
    const int fbase = warp * 16;
    const unsigned FULL = 0xffffffffu;
    const float C3 = DINV3 * DINV3;
    const unsigned in_sa = (unsigned)__cvta_generic_to_shared(in_s);

    // ---- prefetch chunk 0 ----
    {
#pragma unroll
        for (int it = 0; it < 3; it++) {
            int v = tid + it * 256;
            if (v < 576) {
                int r = v >> 3, c4 = v & 7;
                int t = -2 + r;
                bool valid = (unsigned)t < RT;
                int tc = valid ? t : 0;
                const float* src = g_h2 + ((size_t)b * RT + tc) * C2 + c4 * 4;
                cp_async16(in_sa + (unsigned)(r * SIN2 + c4 * 4) * 4, src, valid ? 16 : 0);
            }
        }
        asm volatile("cp.async.commit_group;");
    }

    for (int i = tid; i < HID * HID; i += 256) {
        int k = i >> 7, m = i & 127;
        W2s[m * SW2 + k] = __uint_as_float(f2tf32(W2[i]));
    }
    for (int i = tid; i < 128 * SG1; i += 256) g1s[i] = 0.f;
    unsigned aw1[4][4];
#pragma unroll
    for (int ks = 0; ks < 4; ks++) {
        int k0 = ks * 8 + tq;
        aw1[ks][0] = f2tf32(W1[k0 * HID + fbase + gq]);
        aw1[ks][1] = f2tf32(W1[k0 * HID + fbase + 8 + gq]);
        aw1[ks][2] = f2tf32(W1[(k0 + 4) * HID + fbase + gq]);
        aw1[ks][3] = f2tf32(W1[(k0 + 4) * HID + fbase + 8 + gq]);
    }
    const float b1v0 = b1[fbase + gq], b1v1 = b1[fbase + 8 + gq];
    const float b2v0 = b2[fbase + gq], b2v1 = b2[fbase + 8 + gq];
    float sum0 = 0.f, sum1 = 0.f;

    for (int chunk = 0; chunk < 8; chunk++) {
        const int t0 = chunk * 64;
        const bool bound = (chunk == 0) || (chunk == 7);
        asm volatile("cp.async.wait_group 0;");
        __syncthreads();

        // ---- GEMM1 ----
        float acc[9][4];
#pragma unroll
        for (int nt = 0; nt < 9; nt++)
#pragma unroll
            for (int q = 0; q < 4; q++) acc[nt][q] = 0.f;
#pragma unroll
        for (int ks = 0; ks < 4; ks++)
#pragma unroll
            for (int nt = 0; nt < 9; nt++) {
                unsigned bb0 = f2tf32(in_s[(nt * 8 + gq) * SIN2 + ks * 8 + tq]);
                unsigned bb1 = f2tf32(in_s[(nt * 8 + gq) * SIN2 + ks * 8 + tq + 4]);
                mma_tf32(acc[nt], aw1[ks][0], aw1[ks][1], aw1[ks][2], aw1[ks][3], bb0, bb1);
            }

        // ---- stencil1 + bias + relu + tf32 -> g1s (n in 1..66) ----
#pragma unroll
        for (int h = 0; h < 2; h++) {
            const int rowf = fbase + 8 * h + gq;
            const float bv = h ? b1v1 : b1v0;
#pragma unroll
            for (int nt = 0; nt < 9; nt++) {
                float zE = acc[nt][2 * h], zO = acc[nt][2 * h + 1];
                float pO = __shfl_up_sync(FULL, zO, 1, 4);
                float nEv = __shfl_down_sync(FULL, zE, 1, 4);
                float pT = (nt > 0) ? __shfl_sync(FULL, acc[nt - 1][2 * h + 1], 3, 4) : 0.f;
                float nT = (nt < 8) ? __shfl_sync(FULL, acc[nt + 1][2 * h], 0, 4) : 0.f;
                float Le = (tq == 0) ? pT : pO;
                float Ro = (tq == 3) ? nT : nEv;
                int ne = nt * 8 + 2 * tq;
                int te = t0 - 2 + ne, to = te + 1;
                if (ne >= 2 && ne <= 66) {
                    float y;
                    if (bound)
                        y = ((unsigned)te < RT)
                            ? fmaxf(stencil_apply(te, Le, zE, zO) + bv, 0.f) : 0.f;
                    else
                        y = fmaxf(fmaf(C3, Le, fmaf(C3, zE, C3 * zO)) + bv, 0.f);
                    g1s[rowf * SG1 + ne - 1] = __uint_as_float(f2tf32(y));
                }
                int no = ne + 1;
                if (no <= 66) {
                    float y;
                    if (bound)
                        y = ((unsigned)to < RT)
                            ? fmaxf(stencil_apply(to, zE, zO, Ro) + bv, 0.f) : 0.f;
                    else
                        y = fmaxf(fmaf(C3, zE, fmaf(C3, zO, C3 * Ro)) + bv, 0.f);
                    g1s[rowf * SG1 + no - 1] = __uint_as_float(f2tf32(y));
                }
            }
        }
        __syncthreads();

        // ---- prefetch chunk+1 (overlaps GEMM2) ----
        if (chunk < 7) {
            const int t0n = (chunk + 1) * 64;
#pragma unroll
            for (int it = 0; it < 3; it++) {
                int v = tid + it * 256;
                if (v < 576) {
                    int r = v >> 3, c4 = v & 7;
                    int t = t0n - 2 + r;
                    bool valid = (unsigned)t < RT;
                    int tc = valid ? t : 0;
                    const float* src = g_h2 + ((size_t)b * RT + tc) * C2 + c4 * 4;
                    cp_async16(in_sa + (unsigned)(r * SIN2 + c4 * 4) * 4, src, valid ? 16 : 0);
                }
            }
            asm volatile("cp.async.commit_group;");
        }

        // ---- GEMM2 ----
        float acc2[9][4];
#pragma unroll
        for (int nt = 0; nt < 9; nt++)
#pragma unroll
            for (int q = 0; q < 4; q++) acc2[nt][q] = 0.f;
#pragma unroll 8
        for (int ks = 0; ks < 16; ks++) {
            int k0 = ks * 8 + tq;
            unsigned a0 = __float_as_uint(W2s[(fbase + gq) * SW2 + k0]);
            unsigned a1 = __float_as_uint(W2s[(fbase + 8 + gq) * SW2 + k0]);
            unsigned a2 = __float_as_uint(W2s[(fbase + gq) * SW2 + k0 + 4]);
            unsigned a3 = __float_as_uint(W2s[(fbase + 8 + gq) * SW2 + k0 + 4]);
#pragma unroll
            for (int nt = 0; nt < 9; nt++) {
                unsigned bb0 = __float_as_uint(g1s[k0 * SG1 + nt * 8 + gq]);
                unsigned bb1 = __float_as_uint(g1s[(k0 + 4) * SG1 + nt * 8 + gq]);
                mma_tf32(acc2[nt], a0, a1, a2, a3, bb0, bb1);
            }
        }

        // ---- stencil2 + bias + relu + accumulate mean (n in 1..64) ----
#pragma unroll
        for (int h = 0; h < 2; h++) {
            const float bv = h ? b2v1 : b2v0;
            float lsum = 0.f;
#pragma unroll
            for (int nt = 0; nt < 9; nt++) {
                float zE = acc2[nt][2 * h], zO = acc2[nt][2 * h + 1];
                float pO = __shfl_up_sync(FULL, zO, 1, 4);
                float nEv = __shfl_down_sync(FULL, zE, 1, 4);
                float pT = (nt > 0) ? __shfl_sync(FULL, acc2[nt - 1][2 * h + 1], 3, 4) : 0.f;
                float nT = (nt < 8) ? __shfl_sync(FULL, acc2[nt + 1][2 * h], 0, 4) : 0.f;
                float Le = (tq == 0) ? pT : pO;
                float Ro = (tq == 3) ? nT : nEv;
                int ne = nt * 8 + 2 * tq;
                int te = t0 - 1 + ne, to = te + 1;
                if (ne >= 2 && ne <= 64) {
                    if (bound)
                        lsum += fmaxf(stencil_apply(te, Le, zE, zO) + bv, 0.f);
                    else
                        lsum += fmaxf(fmaf(C3, Le, fmaf(C3, zE, C3 * zO)) + bv, 0.f);
                }
                int no = ne + 1;
                if (no <= 64) {
                    if (bound)
                        lsum += fmaxf(stencil_apply(to, zE, zO, Ro) + bv, 0.f);
                    else
                        lsum += fmaxf(fmaf(C3, zE, fmaf(C3, zO, C3 * Ro)) + bv, 0.f);
                }
            }
            if (h) sum1 += lsum; else sum0 += lsum;
        }
    }

    // ---- epilogue: mean + FC ----
    sum0 += __shfl_xor_sync(FULL, sum0, 1);
    sum0 += __shfl_xor_sync(FULL, sum0, 2);
    sum1 += __shfl_xor_sync(FULL, sum1, 1);
    sum1 += __shfl_xor_sync(FULL, sum1, 2);
    if (tq == 0) {
        in_s[fbase + gq]     = sum0 * (1.f / (float)RT);
        in_s[fbase + 8 + gq] = sum1 * (1.f / (float)RT);
    }
    __syncthreads();
    for (int i = tid; i < HID * OUTF; i += 256) g1s[i] = fcw[i];
    __syncthreads();
    if (tid < OUTF) {
        float acc = fcb[tid];
#pragma unroll 8
        for (int f = 0; f < HID; f++) acc = fmaf(in_s[f], g1s[f * OUTF + tid], acc);
        out[(size_t)b * OUTF + tid] = acc;
    }
}

// ---------------- launch ----------------
extern "C" void kernel_launch(void* const* d_in, const int* in_sizes, int n_in,
                              void* d_out, int out_size) {
    const float* x       = (const float*)d_in[0];
    const float* conv1_w = (const float*)d_in[1];
    const float* conv1_b = (const float*)d_in[2];
    const float* conv2_w = (const float*)d_in[3];
    const float* conv2_b = (const float*)d_in[4];
    const float* gcn1_w  = (const float*)d_in[5];
    const float* gcn1_b  = (const float*)d_in[6];
    const float* gcn2_w  = (const float*)d_in[7];
    const float* gcn2_b  = (const float*)d_in[8];
    const float* fc_w    = (const float*)d_in[9];
    const float* fc_b    = (const float*)d_in[10];
    float* out = (float*)d_out;

    static bool attr_set = false;
    if (!attr_set) {
        cudaFuncSetAttribute(conv12_kernel,
                             cudaFuncAttributeMaxDynamicSharedMemorySize, CONV_SMEM_BYTES);
        cudaFuncSetAttribute(gcn_fused_kernel,
                             cudaFuncAttributeMaxDynamicSharedMemorySize, GCN_SMEM_BYTES);
        attr_set = true;
    }

    conv12_kernel<<<dim3(2, B_), 256, CONV_SMEM_BYTES>>>(x, conv1_w, conv1_b,
                                                         conv2_w, conv2_b);
    gcn_fused_kernel<<<B_, 256, GCN_SMEM_BYTES>>>(gcn1_w, gcn1_b, gcn2_w, gcn2_b,
                                                  fc_w, fc_b, out);
}